// round 1
// baseline (speedup 1.0000x reference)
#include <cuda_runtime.h>

// ---------------- sizes / offsets ----------------
#define NU 200000
#define NN 100000
#define NS 5000
#define NF 200000
#define NTOT 505000   // total rows across types

// row offsets (type-concatenated layout)
#define OFF_U 0
#define OFF_N 200000
#define OFF_S 300000
#define OFF_F 305000

// rs (rsqrt-degree) array offsets inside g_rs
#define RS_PU  0        // posts_u  (user)     200000
#define RS_PN  200000   // posts_n  (news)     100000
#define RS_PS  300000   // pub_s    (source)     5000
#define RS_PBN 305000   // pub_n    (news)     100000
#define RS_FF  405000   // fol_f    (follower) 200000
#define RS_FU  605000   // fol_u    (user)     200000
#define RS_TOT 805000

#define E_POSTS 500000
#define E_PUB   100000
#define E_FOL   1000000

// d_out layout (floats)
#define LOG_U 0
#define LOG_N 400000
#define LOG_S 600000
#define LOG_F 610000
#define H1_BASE 1010000

// ---------------- scratch (device globals; no allocations allowed) -------
__device__ float g_h  [NTOT * 128];   // 258.6 MB
__device__ float g_h2 [NTOT * 128];   // 258.6 MB
__device__ float g_agg[NU * 128];     // 102.4 MB (largest dst type)
__device__ float g_rs [RS_TOT];

// ---------------- utility kernels ----------------
__global__ void fill0_k(float4* p, size_t n4) {
    size_t i = (size_t)blockIdx.x * blockDim.x + threadIdx.x;
    size_t stride = (size_t)gridDim.x * blockDim.x;
    float4 z = make_float4(0.f, 0.f, 0.f, 0.f);
    for (; i < n4; i += stride) p[i] = z;
}

__global__ void count_k(const int* __restrict__ idx, float* __restrict__ deg, int E) {
    int i = blockIdx.x * blockDim.x + threadIdx.x;
    if (i < E) atomicAdd(&deg[idx[i]], 1.0f);
}

__global__ void rsqrt_k(float* __restrict__ v, int n) {
    int i = blockIdx.x * blockDim.x + threadIdx.x;
    if (i < n) v[i] = rsqrtf(fmaxf(v[i], 1.0f));
}

// ---------------- edge scatter: agg[dst] += h[src] * rs_src[src] ---------
// one warp per edge, 128 floats = 32 lanes x float4
__global__ __launch_bounds__(256) void scatter_k(
    const float* __restrict__ h, const int* __restrict__ src,
    const int* __restrict__ dst, const float* __restrict__ rs,
    float* __restrict__ agg, int E)
{
    int warp = blockIdx.x * 8 + (threadIdx.x >> 5);
    int lane = threadIdx.x & 31;
    if (warp >= E) return;
    int s = src[warp];
    int d = dst[warp];
    float r = rs[s];
    float4 v = *(const float4*)(h + (size_t)s * 128 + lane * 4);
    float* ap = agg + (size_t)d * 128 + lane * 4;
    atomicAdd(ap + 0, v.x * r);
    atomicAdd(ap + 1, v.y * r);
    atomicAdd(ap + 2, v.z * r);
    atomicAdd(ap + 3, v.w * r);
}

// ---------------- GEMM: C = f( (A .* rsRow) @ W + bias [+ C] ) -----------
// A: M x K row-major, W: K x 128 row-major, C: M x 128.
// accumulate: C += result (for relation sums). finalize: scale + leakyReLU.
// Requires K % 4 == 0 (128 and 300 both satisfy).
__global__ __launch_bounds__(256) void gemm_k(
    const float* __restrict__ A, int M, int K,
    const float* __restrict__ rsRow,
    const float* __restrict__ W, const float* __restrict__ bias,
    float* __restrict__ C, int accumulate, float finalScale, int finalize)
{
    __shared__ float As[16][68];    // transposed A tile, padded for LDS.128 alignment
    __shared__ float Bs[16][128];

    int tid = threadIdx.x;
    int row0 = blockIdx.x * 64;
    int tx = tid & 15;        // 16 col groups x 8 cols
    int ty = tid >> 4;        // 16 row groups x 4 rows

    int a_row = tid >> 2;           // 0..63
    int a_kq  = (tid & 3) << 2;     // 0,4,8,12
    int b_k   = tid >> 5;           // 0..7
    int b_col = (tid & 31) << 2;    // 0..124

    int gr_a = row0 + a_row;
    float rsA = 1.0f;
    if (rsRow != nullptr && gr_a < M) rsA = rsRow[gr_a];

    float acc[4][8];
#pragma unroll
    for (int i = 0; i < 4; i++)
#pragma unroll
        for (int j = 0; j < 8; j++) acc[i][j] = 0.f;

    for (int k0 = 0; k0 < K; k0 += 16) {
        // load A tile (scaled by per-row rsqrt deg if requested)
        float4 av = make_float4(0.f, 0.f, 0.f, 0.f);
        int gk = k0 + a_kq;
        if (gr_a < M && gk + 3 < K)
            av = *(const float4*)(A + (size_t)gr_a * K + gk);
        As[a_kq + 0][a_row] = av.x * rsA;
        As[a_kq + 1][a_row] = av.y * rsA;
        As[a_kq + 2][a_row] = av.z * rsA;
        As[a_kq + 3][a_row] = av.w * rsA;
        // load B tile (W rows)
#pragma unroll
        for (int hh = 0; hh < 2; hh++) {
            int kb = b_k + hh * 8;
            int gkb = k0 + kb;
            float4 bv = make_float4(0.f, 0.f, 0.f, 0.f);
            if (gkb < K) bv = *(const float4*)(W + (size_t)gkb * 128 + b_col);
            *(float4*)(&Bs[kb][b_col]) = bv;
        }
        __syncthreads();
#pragma unroll
        for (int kk = 0; kk < 16; kk++) {
            float4 a4 = *(const float4*)(&As[kk][ty << 2]);
            float4 b0 = *(const float4*)(&Bs[kk][tx << 3]);
            float4 b1 = *(const float4*)(&Bs[kk][(tx << 3) + 4]);
            float a[4] = {a4.x, a4.y, a4.z, a4.w};
            float b[8] = {b0.x, b0.y, b0.z, b0.w, b1.x, b1.y, b1.z, b1.w};
#pragma unroll
            for (int i = 0; i < 4; i++)
#pragma unroll
                for (int j = 0; j < 8; j++)
                    acc[i][j] += a[i] * b[j];
        }
        __syncthreads();
    }

    // epilogue
#pragma unroll
    for (int i = 0; i < 4; i++) {
        int gr = row0 + (ty << 2) + i;
        if (gr >= M) continue;
#pragma unroll
        for (int jv = 0; jv < 2; jv++) {
            int gc = (tx << 3) + jv * 4;
            float4 c;
            c.x = acc[i][jv * 4 + 0] + bias[gc + 0];
            c.y = acc[i][jv * 4 + 1] + bias[gc + 1];
            c.z = acc[i][jv * 4 + 2] + bias[gc + 2];
            c.w = acc[i][jv * 4 + 3] + bias[gc + 3];
            float4* cp = (float4*)(C + (size_t)gr * 128 + gc);
            if (accumulate) {
                float4 prev = *cp;
                c.x += prev.x; c.y += prev.y; c.z += prev.z; c.w += prev.w;
            }
            if (finalize) {
                c.x *= finalScale; c.y *= finalScale;
                c.z *= finalScale; c.w *= finalScale;
                c.x = c.x > 0.f ? c.x : 0.01f * c.x;
                c.y = c.y > 0.f ? c.y : 0.01f * c.y;
                c.z = c.z > 0.f ? c.z : 0.01f * c.z;
                c.w = c.w > 0.f ? c.w : 0.01f * c.w;
            }
            *cp = c;
        }
    }
}

// ---------------- logits head: out[n][0:2] = h1[n] @ Wl + bl -------------
// one warp per row
__global__ __launch_bounds__(256) void logits_k(
    const float* __restrict__ h1, const float* __restrict__ Wl,
    const float* __restrict__ bl, float* __restrict__ out, int Nrows)
{
    int warp = blockIdx.x * 8 + (threadIdx.x >> 5);
    int lane = threadIdx.x & 31;
    if (warp >= Nrows) return;
    float4 v = *(const float4*)(h1 + (size_t)warp * 128 + lane * 4);
    // Wl is [128][2]; 8 consecutive floats cover rows lane*4..lane*4+3
    const float4* wp = (const float4*)(Wl + lane * 8);
    float4 wa = wp[0];  // rows l4:   (c0,c1), l4+1: (c0,c1)
    float4 wb = wp[1];  // rows l4+2: (c0,c1), l4+3: (c0,c1)
    float s0 = v.x * wa.x + v.y * wa.z + v.z * wb.x + v.w * wb.z;
    float s1 = v.x * wa.y + v.y * wa.w + v.z * wb.y + v.w * wb.w;
#pragma unroll
    for (int off = 16; off > 0; off >>= 1) {
        s0 += __shfl_down_sync(0xffffffffu, s0, off);
        s1 += __shfl_down_sync(0xffffffffu, s1, off);
    }
    if (lane == 0) {
        out[(size_t)warp * 2 + 0] = s0 + bl[0];
        out[(size_t)warp * 2 + 1] = s1 + bl[1];
    }
}

// ---------------- host orchestration ----------------
static void conv_layer(const float* hIn, float* hOut,
                       const float* Wc, const float* bc,
                       void* const* d_in, float* agg, float* rs)
{
    // relation tables (r: 0 posts u->n, 1 n->u, 2 pub s->n, 3 n->s, 4 fol f->u, 5 u->f)
    static const int relSrcOff[6] = {OFF_U, OFF_N, OFF_S, OFF_N, OFF_F, OFF_U};
    static const int relNDst[6]   = {NN, NU, NN, NS, NU, NF};
    static const int relE[6]      = {E_POSTS, E_POSTS, E_PUB, E_PUB, E_FOL, E_FOL};
    static const int relSrcIn[6]  = {26, 27, 28, 29, 30, 31};
    static const int relDstIn[6]  = {27, 26, 29, 28, 31, 30};
    static const int relRsSrc[6]  = {RS_PU, RS_PN, RS_PS, RS_PBN, RS_FF, RS_FU};
    static const int relRsDst[6]  = {RS_PN, RS_PU, RS_PBN, RS_PS, RS_FU, RS_FF};
    static const int typeOff[4]   = {OFF_U, OFF_N, OFF_S, OFF_F};
    static const int dstRels[4][2] = {{1, 4}, {0, 2}, {3, -1}, {5, -1}};
    static const int dstCnt[4]    = {2, 2, 1, 1};

    for (int t = 0; t < 4; t++) {
        for (int j = 0; j < dstCnt[t]; j++) {
            int r = dstRels[t][j];
            int nd = relNDst[r];
            size_t n4 = ((size_t)nd * 128) / 4;
            fill0_k<<<2048, 256>>>((float4*)agg, n4);
            scatter_k<<<(relE[r] + 7) / 8, 256>>>(
                hIn + (size_t)relSrcOff[r] * 128,
                (const int*)d_in[relSrcIn[r]], (const int*)d_in[relDstIn[r]],
                rs + relRsSrc[r], agg, relE[r]);
            gemm_k<<<(nd + 63) / 64, 256>>>(
                agg, nd, 128, rs + relRsDst[r],
                Wc + (size_t)(t * 6 + r) * 16384, bc + (size_t)(t * 6 + r) * 128,
                hOut + (size_t)typeOff[t] * 128,
                /*accumulate*/ (j > 0) ? 1 : 0,
                /*finalScale*/ 1.0f / (float)dstCnt[t],
                /*finalize*/ (j == dstCnt[t] - 1) ? 1 : 0);
        }
    }
}

extern "C" void kernel_launch(void* const* d_in, const int* in_sizes, int n_in,
                              void* d_out, int out_size)
{
    (void)in_sizes; (void)n_in; (void)out_size;

    const float* x_user     = (const float*)d_in[0];
    const float* x_news     = (const float*)d_in[1];
    const float* x_source   = (const float*)d_in[2];
    const float* x_follower = (const float*)d_in[3];
    const float* Wi1[4] = {(const float*)d_in[4], (const float*)d_in[6],
                           (const float*)d_in[8], (const float*)d_in[10]};
    const float* bi1[4] = {(const float*)d_in[5], (const float*)d_in[7],
                           (const float*)d_in[9], (const float*)d_in[11]};
    const float* Wi2 = (const float*)d_in[12];
    const float* bi2 = (const float*)d_in[13];
    const float* c1W = (const float*)d_in[14];
    const float* c1b = (const float*)d_in[15];
    const float* c2W = (const float*)d_in[16];
    const float* c2b = (const float*)d_in[17];
    const float* Wl[4] = {(const float*)d_in[18], (const float*)d_in[20],
                          (const float*)d_in[22], (const float*)d_in[24]};
    const float* bl[4] = {(const float*)d_in[19], (const float*)d_in[21],
                          (const float*)d_in[23], (const float*)d_in[25]};

    float* out = (float*)d_out;

    float *h, *h2, *agg, *rs;
    cudaGetSymbolAddress((void**)&h,   g_h);
    cudaGetSymbolAddress((void**)&h2,  g_h2);
    cudaGetSymbolAddress((void**)&agg, g_agg);
    cudaGetSymbolAddress((void**)&rs,  g_rs);

    static const int typeOff[4] = {OFF_U, OFF_N, OFF_S, OFF_F};
    static const int typeN[4]   = {NU, NN, NS, NF};
    static const int logOff[4]  = {LOG_U, LOG_N, LOG_S, LOG_F};

    // ---- degrees -> rsqrt(max(deg,1)) ----
    fill0_k<<<512, 256>>>((float4*)rs, RS_TOT / 4);
    count_k<<<(E_POSTS + 255) / 256, 256>>>((const int*)d_in[26], rs + RS_PU,  E_POSTS);
    count_k<<<(E_POSTS + 255) / 256, 256>>>((const int*)d_in[27], rs + RS_PN,  E_POSTS);
    count_k<<<(E_PUB   + 255) / 256, 256>>>((const int*)d_in[28], rs + RS_PS,  E_PUB);
    count_k<<<(E_PUB   + 255) / 256, 256>>>((const int*)d_in[29], rs + RS_PBN, E_PUB);
    count_k<<<(E_FOL   + 255) / 256, 256>>>((const int*)d_in[30], rs + RS_FF,  E_FOL);
    count_k<<<(E_FOL   + 255) / 256, 256>>>((const int*)d_in[31], rs + RS_FU,  E_FOL);
    rsqrt_k<<<(RS_TOT + 255) / 256, 256>>>(rs, RS_TOT);

    // ---- input layer 1: h = lrelu(x @ Wi1 + bi1) ----
    const float* xs[4] = {x_user, x_news, x_source, x_follower};
    const int    inK[4] = {128, 300, 128, 128};
    for (int t = 0; t < 4; t++) {
        gemm_k<<<(typeN[t] + 63) / 64, 256>>>(
            xs[t], typeN[t], inK[t], nullptr, Wi1[t], bi1[t],
            h + (size_t)typeOff[t] * 128, 0, 1.0f, 1);
    }

    // ---- input layer 2: h2 = lrelu(h @ Wi2[t] + bi2[t]) ----
    for (int t = 0; t < 4; t++) {
        gemm_k<<<(typeN[t] + 63) / 64, 256>>>(
            h + (size_t)typeOff[t] * 128, typeN[t], 128, nullptr,
            Wi2 + (size_t)t * 16384, bi2 + (size_t)t * 128,
            h2 + (size_t)typeOff[t] * 128, 0, 1.0f, 1);
    }

    // ---- conv1: h2 -> h ----
    conv_layer(h2, h, c1W, c1b, d_in, agg, rs);

    // ---- conv2: h -> h1 (directly into d_out's h1 region) ----
    float* h1 = out + H1_BASE;
    conv_layer(h, h1, c2W, c2b, d_in, agg, rs);

    // ---- logits ----
    for (int t = 0; t < 4; t++) {
        logits_k<<<(typeN[t] + 7) / 8, 256>>>(
            h1 + (size_t)typeOff[t] * 128, Wl[t], bl[t],
            out + logOff[t], typeN[t]);
    }
}

// round 5
// speedup vs baseline: 1.4413x; 1.4413x over previous
#include <cuda_runtime.h>

// ---------------- sizes / offsets ----------------
#define NU 200000
#define NN 100000
#define NS 5000
#define NF 200000
#define NTOT 505000

#define OFF_U 0
#define OFF_N 200000
#define OFF_S 300000
#define OFF_F 305000

#define RS_PU  0
#define RS_PN  200000
#define RS_PS  300000
#define RS_PBN 305000
#define RS_FF  405000
#define RS_FU  605000
#define RS_TOT 805000

#define E_POSTS 500000
#define E_PUB   100000
#define E_FOL   1000000

#define LOG_U 0
#define LOG_N 400000
#define LOG_S 600000
#define LOG_F 610000
#define H1_BASE 1010000

// ---------------- scratch ----------------
__device__ float g_h  [NTOT * 128];
__device__ float g_h2 [NTOT * 128];
__device__ float g_agg[NU * 128];
__device__ float g_rs [RS_TOT];

// ---------------- utility kernels ----------------
__global__ void fill0_k(float4* p, size_t n4) {
    size_t i = (size_t)blockIdx.x * blockDim.x + threadIdx.x;
    size_t stride = (size_t)gridDim.x * blockDim.x;
    float4 z = make_float4(0.f, 0.f, 0.f, 0.f);
    for (; i < n4; i += stride) p[i] = z;
}

__global__ void count_k(const int* __restrict__ idx, float* __restrict__ deg, int E) {
    int i = blockIdx.x * blockDim.x + threadIdx.x;
    if (i < E) atomicAdd(&deg[idx[i]], 1.0f);
}

__global__ void rsqrt_k(float* __restrict__ v, int n) {
    int i = blockIdx.x * blockDim.x + threadIdx.x;
    if (i < n) v[i] = rsqrtf(fmaxf(v[i], 1.0f));
}

// ---------------- edge scatter: agg[dst] += h[src] * rs_src[src] ---------
__global__ __launch_bounds__(256) void scatter_k(
    const float* __restrict__ h, const int* __restrict__ src,
    const int* __restrict__ dst, const float* __restrict__ rs,
    float* __restrict__ agg, int E)
{
    int warp = blockIdx.x * 8 + (threadIdx.x >> 5);
    int lane = threadIdx.x & 31;
    if (warp >= E) return;
    int s = src[warp];
    int d = dst[warp];
    float r = rs[s];
    float4 v = *(const float4*)(h + (size_t)s * 128 + lane * 4);
    float* ap = agg + (size_t)d * 128 + lane * 4;
    float vx = v.x * r, vy = v.y * r, vz = v.z * r, vw = v.w * r;
    asm volatile("red.global.add.v4.f32 [%0], {%1, %2, %3, %4};"
                 :: "l"(ap), "f"(vx), "f"(vy), "f"(vz), "f"(vw) : "memory");
}

// ---------------- GEMM v2: 128x128 tile, 8x8/thread, reg-prefetch --------
// C = f( (A .* rsRow) @ W + bias [+ C] ); A: MxK, W: Kx128, K % 4 == 0
__global__ __launch_bounds__(256, 2) void gemm2_k(
    const float* __restrict__ A, int M, int K,
    const float* __restrict__ rsRow,
    const float* __restrict__ W, const float* __restrict__ bias,
    float* __restrict__ C, int accumulate, float finalScale, int finalize)
{
    __shared__ float As[16][132];   // [k][row], pad 132: 528B stride, 16B aligned, conflict-free
    __shared__ float Bs[16][132];

    int tid = threadIdx.x;
    int row0 = blockIdx.x * 128;
    int tx = tid & 15;          // output col group (8 cols)
    int ty = tid >> 4;          // output row group (8 rows)

    // A loader: 2 float4 per thread (512 total)
    int aRow[2], aKq[2];
    float rsAv[2];
    // B loader: 2 float4 per thread
    int bKk[2], bCol[2];
#pragma unroll
    for (int i = 0; i < 2; i++) {
        int id = tid + 256 * i;
        aRow[i] = id >> 2;
        aKq[i]  = (id & 3) << 2;
        bKk[i]  = id >> 5;
        bCol[i] = (id & 31) << 2;
        int gr = row0 + aRow[i];
        rsAv[i] = (rsRow != nullptr && gr < M) ? rsRow[gr] : 1.0f;
    }

    float acc[8][8];
#pragma unroll
    for (int i = 0; i < 8; i++)
#pragma unroll
        for (int j = 0; j < 8; j++) acc[i][j] = 0.f;

    const float4 z4 = make_float4(0.f, 0.f, 0.f, 0.f);
    float4 pA[2], pB[2];
#pragma unroll
    for (int i = 0; i < 2; i++) {
        int gr = row0 + aRow[i], gk = aKq[i];
        pA[i] = (gr < M && gk < K) ? *(const float4*)(A + (size_t)gr * K + gk) : z4;
        int gkb = bKk[i];
        pB[i] = (gkb < K) ? *(const float4*)(W + (size_t)gkb * 128 + bCol[i]) : z4;
    }

    for (int k0 = 0; k0 < K; k0 += 16) {
        // commit prefetched tile to smem
#pragma unroll
        for (int i = 0; i < 2; i++) {
            As[aKq[i] + 0][aRow[i]] = pA[i].x * rsAv[i];
            As[aKq[i] + 1][aRow[i]] = pA[i].y * rsAv[i];
            As[aKq[i] + 2][aRow[i]] = pA[i].z * rsAv[i];
            As[aKq[i] + 3][aRow[i]] = pA[i].w * rsAv[i];
            *(float4*)(&Bs[bKk[i]][bCol[i]]) = pB[i];
        }
        __syncthreads();

        // prefetch next tile into registers
        int kn = k0 + 16;
        if (kn < K) {
#pragma unroll
            for (int i = 0; i < 2; i++) {
                int gr = row0 + aRow[i], gk = kn + aKq[i];
                pA[i] = (gr < M && gk < K) ? *(const float4*)(A + (size_t)gr * K + gk) : z4;
                int gkb = kn + bKk[i];
                pB[i] = (gkb < K) ? *(const float4*)(W + (size_t)gkb * 128 + bCol[i]) : z4;
            }
        }

        // compute
#pragma unroll
        for (int kk = 0; kk < 16; kk++) {
            float4 a0 = *(const float4*)(&As[kk][ty << 3]);
            float4 a1 = *(const float4*)(&As[kk][(ty << 3) + 4]);
            float4 b0 = *(const float4*)(&Bs[kk][tx << 3]);
            float4 b1 = *(const float4*)(&Bs[kk][(tx << 3) + 4]);
            float a[8] = {a0.x, a0.y, a0.z, a0.w, a1.x, a1.y, a1.z, a1.w};
            float b[8] = {b0.x, b0.y, b0.z, b0.w, b1.x, b1.y, b1.z, b1.w};
#pragma unroll
            for (int i = 0; i < 8; i++)
#pragma unroll
                for (int j = 0; j < 8; j++)
                    acc[i][j] += a[i] * b[j];
        }
        __syncthreads();
    }

    // epilogue
#pragma unroll
    for (int i = 0; i < 8; i++) {
        int gr = row0 + (ty << 3) + i;
        if (gr >= M) continue;
#pragma unroll
        for (int jv = 0; jv < 2; jv++) {
            int gc = (tx << 3) + jv * 4;
            float4 c;
            c.x = acc[i][jv * 4 + 0] + bias[gc + 0];
            c.y = acc[i][jv * 4 + 1] + bias[gc + 1];
            c.z = acc[i][jv * 4 + 2] + bias[gc + 2];
            c.w = acc[i][jv * 4 + 3] + bias[gc + 3];
            float4* cp = (float4*)(C + (size_t)gr * 128 + gc);
            if (accumulate) {
                float4 prev = *cp;
                c.x += prev.x; c.y += prev.y; c.z += prev.z; c.w += prev.w;
            }
            if (finalize) {
                c.x *= finalScale; c.y *= finalScale;
                c.z *= finalScale; c.w *= finalScale;
                c.x = c.x > 0.f ? c.x : 0.01f * c.x;
                c.y = c.y > 0.f ? c.y : 0.01f * c.y;
                c.z = c.z > 0.f ? c.z : 0.01f * c.z;
                c.w = c.w > 0.f ? c.w : 0.01f * c.w;
            }
            *cp = c;
        }
    }
}

// ---------------- logits head ----------------
__global__ __launch_bounds__(256) void logits_k(
    const float* __restrict__ h1, const float* __restrict__ Wl,
    const float* __restrict__ bl, float* __restrict__ out, int Nrows)
{
    int warp = blockIdx.x * 8 + (threadIdx.x >> 5);
    int lane = threadIdx.x & 31;
    if (warp >= Nrows) return;
    float4 v = *(const float4*)(h1 + (size_t)warp * 128 + lane * 4);
    const float4* wp = (const float4*)(Wl + lane * 8);
    float4 wa = wp[0];
    float4 wb = wp[1];
    float s0 = v.x * wa.x + v.y * wa.z + v.z * wb.x + v.w * wb.z;
    float s1 = v.x * wa.y + v.y * wa.w + v.z * wb.y + v.w * wb.w;
#pragma unroll
    for (int off = 16; off > 0; off >>= 1) {
        s0 += __shfl_down_sync(0xffffffffu, s0, off);
        s1 += __shfl_down_sync(0xffffffffu, s1, off);
    }
    if (lane == 0) {
        out[(size_t)warp * 2 + 0] = s0 + bl[0];
        out[(size_t)warp * 2 + 1] = s1 + bl[1];
    }
}

// ---------------- host orchestration ----------------
static void conv_layer(const float* hIn, float* hOut,
                       const float* Wc, const float* bc,
                       void* const* d_in, float* agg, float* rs)
{
    static const int relSrcOff[6] = {OFF_U, OFF_N, OFF_S, OFF_N, OFF_F, OFF_U};
    static const int relNDst[6]   = {NN, NU, NN, NS, NU, NF};
    static const int relE[6]      = {E_POSTS, E_POSTS, E_PUB, E_PUB, E_FOL, E_FOL};
    static const int relSrcIn[6]  = {26, 27, 28, 29, 30, 31};
    static const int relDstIn[6]  = {27, 26, 29, 28, 31, 30};
    static const int relRsSrc[6]  = {RS_PU, RS_PN, RS_PS, RS_PBN, RS_FF, RS_FU};
    static const int relRsDst[6]  = {RS_PN, RS_PU, RS_PBN, RS_PS, RS_FU, RS_FF};
    static const int typeOff[4]   = {OFF_U, OFF_N, OFF_S, OFF_F};
    static const int dstRels[4][2] = {{1, 4}, {0, 2}, {3, -1}, {5, -1}};
    static const int dstCnt[4]    = {2, 2, 1, 1};

    for (int t = 0; t < 4; t++) {
        for (int j = 0; j < dstCnt[t]; j++) {
            int r = dstRels[t][j];
            int nd = relNDst[r];
            size_t n4 = ((size_t)nd * 128) / 4;
            fill0_k<<<2048, 256>>>((float4*)agg, n4);
            scatter_k<<<(relE[r] + 7) / 8, 256>>>(
                hIn + (size_t)relSrcOff[r] * 128,
                (const int*)d_in[relSrcIn[r]], (const int*)d_in[relDstIn[r]],
                rs + relRsSrc[r], agg, relE[r]);
            gemm2_k<<<(nd + 127) / 128, 256>>>(
                agg, nd, 128, rs + relRsDst[r],
                Wc + (size_t)(t * 6 + r) * 16384, bc + (size_t)(t * 6 + r) * 128,
                hOut + (size_t)typeOff[t] * 128,
                (j > 0) ? 1 : 0,
                1.0f / (float)dstCnt[t],
                (j == dstCnt[t] - 1) ? 1 : 0);
        }
    }
}

extern "C" void kernel_launch(void* const* d_in, const int* in_sizes, int n_in,
                              void* d_out, int out_size)
{
    (void)in_sizes; (void)n_in; (void)out_size;

    const float* x_user     = (const float*)d_in[0];
    const float* x_news     = (const float*)d_in[1];
    const float* x_source   = (const float*)d_in[2];
    const float* x_follower = (const float*)d_in[3];
    const float* Wi1[4] = {(const float*)d_in[4], (const float*)d_in[6],
                           (const float*)d_in[8], (const float*)d_in[10]};
    const float* bi1[4] = {(const float*)d_in[5], (const float*)d_in[7],
                           (const float*)d_in[9], (const float*)d_in[11]};
    const float* Wi2 = (const float*)d_in[12];
    const float* bi2 = (const float*)d_in[13];
    const float* c1W = (const float*)d_in[14];
    const float* c1b = (const float*)d_in[15];
    const float* c2W = (const float*)d_in[16];
    const float* c2b = (const float*)d_in[17];
    const float* Wl[4] = {(const float*)d_in[18], (const float*)d_in[20],
                          (const float*)d_in[22], (const float*)d_in[24]};
    const float* bl[4] = {(const float*)d_in[19], (const float*)d_in[21],
                          (const float*)d_in[23], (const float*)d_in[25]};

    float* out = (float*)d_out;

    float *h, *h2, *agg, *rs;
    cudaGetSymbolAddress((void**)&h,   g_h);
    cudaGetSymbolAddress((void**)&h2,  g_h2);
    cudaGetSymbolAddress((void**)&agg, g_agg);
    cudaGetSymbolAddress((void**)&rs,  g_rs);

    static const int typeOff[4] = {OFF_U, OFF_N, OFF_S, OFF_F};
    static const int typeN[4]   = {NU, NN, NS, NF};
    static const int logOff[4]  = {LOG_U, LOG_N, LOG_S, LOG_F};

    // degrees -> rsqrt(max(deg,1))
    fill0_k<<<512, 256>>>((float4*)rs, RS_TOT / 4);
    count_k<<<(E_POSTS + 255) / 256, 256>>>((const int*)d_in[26], rs + RS_PU,  E_POSTS);
    count_k<<<(E_POSTS + 255) / 256, 256>>>((const int*)d_in[27], rs + RS_PN,  E_POSTS);
    count_k<<<(E_PUB   + 255) / 256, 256>>>((const int*)d_in[28], rs + RS_PS,  E_PUB);
    count_k<<<(E_PUB   + 255) / 256, 256>>>((const int*)d_in[29], rs + RS_PBN, E_PUB);
    count_k<<<(E_FOL   + 255) / 256, 256>>>((const int*)d_in[30], rs + RS_FF,  E_FOL);
    count_k<<<(E_FOL   + 255) / 256, 256>>>((const int*)d_in[31], rs + RS_FU,  E_FOL);
    rsqrt_k<<<(RS_TOT + 255) / 256, 256>>>(rs, RS_TOT);

    // input layer 1
    const float* xs[4] = {x_user, x_news, x_source, x_follower};
    const int    inK[4] = {128, 300, 128, 128};
    for (int t = 0; t < 4; t++) {
        gemm2_k<<<(typeN[t] + 127) / 128, 256>>>(
            xs[t], typeN[t], inK[t], nullptr, Wi1[t], bi1[t],
            h + (size_t)typeOff[t] * 128, 0, 1.0f, 1);
    }

    // input layer 2
    for (int t = 0; t < 4; t++) {
        gemm2_k<<<(typeN[t] + 127) / 128, 256>>>(
            h + (size_t)typeOff[t] * 128, typeN[t], 128, nullptr,
            Wi2 + (size_t)t * 16384, bi2 + (size_t)t * 128,
            h2 + (size_t)typeOff[t] * 128, 0, 1.0f, 1);
    }

    // conv1: h2 -> h
    conv_layer(h2, h, c1W, c1b, d_in, agg, rs);

    // conv2: h -> h1 (into d_out)
    float* h1 = out + H1_BASE;
    conv_layer(h, h1, c2W, c2b, d_in, agg, rs);

    // logits
    for (int t = 0; t < 4; t++) {
        logits_k<<<(typeN[t] + 7) / 8, 256>>>(
            h1 + (size_t)typeOff[t] * 128, Wl[t], bl[t],
            out + logOff[t], typeN[t]);
    }
}

// round 10
// speedup vs baseline: 1.9187x; 1.3312x over previous
#include <cuda_runtime.h>
#include <cuda_bf16.h>
#include <cstdint>

// ---------------- sizes / offsets ----------------
#define NU 200000
#define NN 100000
#define NS 5000
#define NF 200000
#define NTOT 505000

#define OFF_U 0
#define OFF_N 200000
#define OFF_S 300000
#define OFF_F 305000

#define RS_PU  0
#define RS_PN  200000
#define RS_PS  300000
#define RS_PBN 305000
#define RS_FF  405000
#define RS_FU  605000
#define RS_TOT 805000

#define E_POSTS 500000
#define E_PUB   100000
#define E_FOL   1000000

#define LOG_U 0
#define LOG_N 400000
#define LOG_S 600000
#define LOG_F 610000
#define H1_BASE 1010000

// ---------------- scratch ----------------
__device__ float g_h  [NTOT * 128];
__device__ float g_h2 [NTOT * 128];
__device__ float g_agg[NU * 128];
__device__ float g_rs [RS_TOT];

// ---------------- helpers ----------------
__device__ __forceinline__ uint32_t smem_u32(const void* p) {
    uint32_t a;
    asm("{ .reg .u64 t; cvta.to.shared.u64 t, %1; cvt.u32.u64 %0, t; }" : "=r"(a) : "l"(p));
    return a;
}
__device__ __forceinline__ uint32_t pack_bf16(__nv_bfloat16 lo, __nv_bfloat16 hi) {
    return (uint32_t)__bfloat16_as_ushort(lo) | ((uint32_t)__bfloat16_as_ushort(hi) << 16);
}
__device__ __forceinline__ void ldsm_x4(uint32_t* r, uint32_t addr) {
    asm volatile("ldmatrix.sync.aligned.m8n8.x4.shared.b16 {%0,%1,%2,%3}, [%4];"
                 : "=r"(r[0]), "=r"(r[1]), "=r"(r[2]), "=r"(r[3]) : "r"(addr));
}
__device__ __forceinline__ void ldsm_x2t(uint32_t* r, uint32_t addr) {
    asm volatile("ldmatrix.sync.aligned.m8n8.x2.trans.shared.b16 {%0,%1}, [%2];"
                 : "=r"(r[0]), "=r"(r[1]) : "r"(addr));
}
__device__ __forceinline__ void mma_bf16(float* c, const uint32_t* a, const uint32_t* b) {
    asm volatile(
        "mma.sync.aligned.m16n8k16.row.col.f32.bf16.bf16.f32 "
        "{%0,%1,%2,%3}, {%4,%5,%6,%7}, {%8,%9}, {%0,%1,%2,%3};"
        : "+f"(c[0]), "+f"(c[1]), "+f"(c[2]), "+f"(c[3])
        : "r"(a[0]), "r"(a[1]), "r"(a[2]), "r"(a[3]), "r"(b[0]), "r"(b[1]));
}

// ------------- HMMA bf16-split GEMM: C = f((A.*rs)@W + bias [+C]) --------
// A: MxK f32 (K%4==0), W: Kx128 f32, C: Mx128 f32.
// D = Ah*Bh + Ah*Bl + Al*Bh in fp32 accum (bf16 3-split of fp32).
// CTA tile 128x128, 8 warps (warp tile 32x64), K chunked by 32.
// smem: A hi/lo [128 rows][32 k] bf16, row pitch 80B (conflict-free ldmatrix)
//       B hi/lo [32 k rows][128 n] bf16, row pitch 272B (ldmatrix.trans)
#define SA_H 0
#define SA_L 10240
#define SB_H 20480
#define SB_L 29184
#define SM_SZ 37888

__global__ __launch_bounds__(256) void hgemm_k(
    const float* __restrict__ A, int M, int K,
    const float* __restrict__ rsRow,
    const float* __restrict__ W, const float* __restrict__ bias,
    float* __restrict__ C, int accumulate, float finalScale, int finalize)
{
    __shared__ __align__(16) unsigned char sm[SM_SZ];
    uint32_t sb = smem_u32(sm);
    int tid = threadIdx.x;
    int lane = tid & 31;
    int wid = tid >> 5;
    int row0 = blockIdx.x * 128;
    int m0 = (wid & 3) * 32;         // warp m-offset (32 rows)
    int n0w = (wid >> 2) * 64;       // warp n-offset (64 cols)

    float acc[2][8][4];
#pragma unroll
    for (int i = 0; i < 2; i++)
#pragma unroll
        for (int j = 0; j < 8; j++)
#pragma unroll
            for (int q = 0; q < 4; q++) acc[i][j][q] = 0.f;

    for (int kc = 0; kc < K; kc += 32) {
        // ---- stage A chunk: 128 rows x 32 k, hi/lo bf16 ----
#pragma unroll
        for (int it = 0; it < 2; it++) {
            int g = tid + 256 * it;
            int m = g >> 2;
            int c4 = g & 3;              // 16B chunk index (8 bf16)
            int gk = kc + c4 * 8;
            int gr = row0 + m;
            float f[8];
#pragma unroll
            for (int j = 0; j < 8; j++) f[j] = 0.f;
            if (gr < M) {
                float r = (rsRow != nullptr) ? rsRow[gr] : 1.0f;
                const float* ap = A + (size_t)gr * K + gk;
                if (gk < K) {
                    float4 v = *(const float4*)ap;
                    f[0] = v.x * r; f[1] = v.y * r; f[2] = v.z * r; f[3] = v.w * r;
                }
                if (gk + 4 < K) {
                    float4 v = *(const float4*)(ap + 4);
                    f[4] = v.x * r; f[5] = v.y * r; f[6] = v.z * r; f[7] = v.w * r;
                }
            }
            uint32_t ph[4], pl[4];
#pragma unroll
            for (int j = 0; j < 4; j++) {
                __nv_bfloat16 h0 = __float2bfloat16(f[2 * j]);
                __nv_bfloat16 h1 = __float2bfloat16(f[2 * j + 1]);
                __nv_bfloat16 l0 = __float2bfloat16(f[2 * j]     - __bfloat162float(h0));
                __nv_bfloat16 l1 = __float2bfloat16(f[2 * j + 1] - __bfloat162float(h1));
                ph[j] = pack_bf16(h0, h1);
                pl[j] = pack_bf16(l0, l1);
            }
            uint32_t off = (uint32_t)m * 80 + (uint32_t)c4 * 16;
            *(uint4*)(sm + SA_H + off) = make_uint4(ph[0], ph[1], ph[2], ph[3]);
            *(uint4*)(sm + SA_L + off) = make_uint4(pl[0], pl[1], pl[2], pl[3]);
        }
        // ---- stage B chunk: 32 k rows x 128 n (K-major, native W layout) ----
#pragma unroll
        for (int it = 0; it < 2; it++) {
            int g = tid + 256 * it;
            int k = g >> 4;
            int n8 = g & 15;             // 16B chunk (8 n values)
            int gk = kc + k;
            float f[8];
#pragma unroll
            for (int j = 0; j < 8; j++) f[j] = 0.f;
            if (gk < K) {
                const float* wp = W + (size_t)gk * 128 + n8 * 8;
                float4 v0 = *(const float4*)wp;
                float4 v1 = *(const float4*)(wp + 4);
                f[0] = v0.x; f[1] = v0.y; f[2] = v0.z; f[3] = v0.w;
                f[4] = v1.x; f[5] = v1.y; f[6] = v1.z; f[7] = v1.w;
            }
            uint32_t ph[4], pl[4];
#pragma unroll
            for (int j = 0; j < 4; j++) {
                __nv_bfloat16 h0 = __float2bfloat16(f[2 * j]);
                __nv_bfloat16 h1 = __float2bfloat16(f[2 * j + 1]);
                __nv_bfloat16 l0 = __float2bfloat16(f[2 * j]     - __bfloat162float(h0));
                __nv_bfloat16 l1 = __float2bfloat16(f[2 * j + 1] - __bfloat162float(h1));
                ph[j] = pack_bf16(h0, h1);
                pl[j] = pack_bf16(l0, l1);
            }
            uint32_t off = (uint32_t)k * 272 + (uint32_t)n8 * 16;
            *(uint4*)(sm + SB_H + off) = make_uint4(ph[0], ph[1], ph[2], ph[3]);
            *(uint4*)(sm + SB_L + off) = make_uint4(pl[0], pl[1], pl[2], pl[3]);
        }
        __syncthreads();

        // ---- MMA over this 32-k chunk: 2 k16 steps ----
#pragma unroll
        for (int ks = 0; ks < 32; ks += 16) {
            uint32_t ah[2][4], al[2][4];
#pragma unroll
            for (int mf = 0; mf < 2; mf++) {
                uint32_t ra = sb + SA_H
                            + (uint32_t)(m0 + mf * 16 + (lane & 15)) * 80
                            + (uint32_t)((ks >> 3) + (lane >> 4)) * 16;
                ldsm_x4(ah[mf], ra);
                ldsm_x4(al[mf], ra + (SA_L - SA_H));
            }
#pragma unroll
            for (int nf = 0; nf < 8; nf++) {
                uint32_t rb = sb + SB_H
                            + (uint32_t)(ks + (lane & 15)) * 272
                            + (uint32_t)(n0w + nf * 8) * 2;
                uint32_t bh[2], bl[2];
                ldsm_x2t(bh, rb);
                ldsm_x2t(bl, rb + (SB_L - SB_H));
#pragma unroll
                for (int mf = 0; mf < 2; mf++) {
                    mma_bf16(acc[mf][nf], ah[mf], bh);
                    mma_bf16(acc[mf][nf], ah[mf], bl);
                    mma_bf16(acc[mf][nf], al[mf], bh);
                }
            }
        }
        __syncthreads();
    }

    // ---- epilogue ----
    int g4 = lane >> 2;
    int t2 = (lane & 3) * 2;
#pragma unroll
    for (int mf = 0; mf < 2; mf++) {
        int rbase = row0 + m0 + mf * 16 + g4;
#pragma unroll
        for (int nf = 0; nf < 8; nf++) {
            int col = n0w + nf * 8 + t2;
            float2 bb = *(const float2*)(bias + col);
#pragma unroll
            for (int half = 0; half < 2; half++) {
                int r = rbase + half * 8;
                if (r >= M) continue;
                float cx = acc[mf][nf][half * 2 + 0] + bb.x;
                float cy = acc[mf][nf][half * 2 + 1] + bb.y;
                float2* cp = (float2*)(C + (size_t)r * 128 + col);
                if (accumulate) {
                    float2 p = *cp;
                    cx += p.x; cy += p.y;
                }
                if (finalize) {
                    cx *= finalScale; cy *= finalScale;
                    cx = cx > 0.f ? cx : 0.01f * cx;
                    cy = cy > 0.f ? cy : 0.01f * cy;
                }
                *cp = make_float2(cx, cy);
            }
        }
    }
}

// ---------------- utility kernels ----------------
__global__ void fill0_k(float4* p, size_t n4) {
    size_t i = (size_t)blockIdx.x * blockDim.x + threadIdx.x;
    size_t stride = (size_t)gridDim.x * blockDim.x;
    float4 z = make_float4(0.f, 0.f, 0.f, 0.f);
    for (; i < n4; i += stride) p[i] = z;
}

__global__ void count_k(const int* __restrict__ idx, float* __restrict__ deg, int E) {
    int i = blockIdx.x * blockDim.x + threadIdx.x;
    if (i < E) atomicAdd(&deg[idx[i]], 1.0f);
}

__global__ void rsqrt_k(float* __restrict__ v, int n) {
    int i = blockIdx.x * blockDim.x + threadIdx.x;
    if (i < n) v[i] = rsqrtf(fmaxf(v[i], 1.0f));
}

// ---------------- edge scatter ----------------
__global__ __launch_bounds__(256) void scatter_k(
    const float* __restrict__ h, const int* __restrict__ src,
    const int* __restrict__ dst, const float* __restrict__ rs,
    float* __restrict__ agg, int E)
{
    int warp = blockIdx.x * 8 + (threadIdx.x >> 5);
    int lane = threadIdx.x & 31;
    if (warp >= E) return;
    int s = src[warp];
    int d = dst[warp];
    float r = rs[s];
    float4 v = *(const float4*)(h + (size_t)s * 128 + lane * 4);
    float* ap = agg + (size_t)d * 128 + lane * 4;
    float vx = v.x * r, vy = v.y * r, vz = v.z * r, vw = v.w * r;
    asm volatile("red.global.add.v4.f32 [%0], {%1, %2, %3, %4};"
                 :: "l"(ap), "f"(vx), "f"(vy), "f"(vz), "f"(vw) : "memory");
}

// ---------------- logits head ----------------
__global__ __launch_bounds__(256) void logits_k(
    const float* __restrict__ h1, const float* __restrict__ Wl,
    const float* __restrict__ bl, float* __restrict__ out, int Nrows)
{
    int warp = blockIdx.x * 8 + (threadIdx.x >> 5);
    int lane = threadIdx.x & 31;
    if (warp >= Nrows) return;
    float4 v = *(const float4*)(h1 + (size_t)warp * 128 + lane * 4);
    const float4* wp = (const float4*)(Wl + lane * 8);
    float4 wa = wp[0];
    float4 wb = wp[1];
    float s0 = v.x * wa.x + v.y * wa.z + v.z * wb.x + v.w * wb.z;
    float s1 = v.x * wa.y + v.y * wa.w + v.z * wb.y + v.w * wb.w;
#pragma unroll
    for (int off = 16; off > 0; off >>= 1) {
        s0 += __shfl_down_sync(0xffffffffu, s0, off);
        s1 += __shfl_down_sync(0xffffffffu, s1, off);
    }
    if (lane == 0) {
        out[(size_t)warp * 2 + 0] = s0 + bl[0];
        out[(size_t)warp * 2 + 1] = s1 + bl[1];
    }
}

// ---------------- host orchestration ----------------
static void launch_hgemm(const float* A, int M, int K, const float* rsRow,
                         const float* W, const float* bias, float* C,
                         int accumulate, float finalScale, int finalize)
{
    hgemm_k<<<(M + 127) / 128, 256>>>(
        A, M, K, rsRow, W, bias, C, accumulate, finalScale, finalize);
}

static void conv_layer(const float* hIn, float* hOut,
                       const float* Wc, const float* bc,
                       void* const* d_in, float* agg, float* rs)
{
    static const int relSrcOff[6] = {OFF_U, OFF_N, OFF_S, OFF_N, OFF_F, OFF_U};
    static const int relNDst[6]   = {NN, NU, NN, NS, NU, NF};
    static const int relE[6]      = {E_POSTS, E_POSTS, E_PUB, E_PUB, E_FOL, E_FOL};
    static const int relSrcIn[6]  = {26, 27, 28, 29, 30, 31};
    static const int relDstIn[6]  = {27, 26, 29, 28, 31, 30};
    static const int relRsSrc[6]  = {RS_PU, RS_PN, RS_PS, RS_PBN, RS_FF, RS_FU};
    static const int relRsDst[6]  = {RS_PN, RS_PU, RS_PBN, RS_PS, RS_FU, RS_FF};
    static const int typeOff[4]   = {OFF_U, OFF_N, OFF_S, OFF_F};
    static const int dstRels[4][2] = {{1, 4}, {0, 2}, {3, -1}, {5, -1}};
    static const int dstCnt[4]    = {2, 2, 1, 1};

    for (int t = 0; t < 4; t++) {
        for (int j = 0; j < dstCnt[t]; j++) {
            int r = dstRels[t][j];
            int nd = relNDst[r];
            size_t n4 = ((size_t)nd * 128) / 4;
            fill0_k<<<2048, 256>>>((float4*)agg, n4);
            scatter_k<<<(relE[r] + 7) / 8, 256>>>(
                hIn + (size_t)relSrcOff[r] * 128,
                (const int*)d_in[relSrcIn[r]], (const int*)d_in[relDstIn[r]],
                rs + relRsSrc[r], agg, relE[r]);
            launch_hgemm(
                agg, nd, 128, rs + relRsDst[r],
                Wc + (size_t)(t * 6 + r) * 16384, bc + (size_t)(t * 6 + r) * 128,
                hOut + (size_t)typeOff[t] * 128,
                (j > 0) ? 1 : 0,
                1.0f / (float)dstCnt[t],
                (j == dstCnt[t] - 1) ? 1 : 0);
        }
    }
}

extern "C" void kernel_launch(void* const* d_in, const int* in_sizes, int n_in,
                              void* d_out, int out_size)
{
    (void)in_sizes; (void)n_in; (void)out_size;

    const float* x_user     = (const float*)d_in[0];
    const float* x_news     = (const float*)d_in[1];
    const float* x_source   = (const float*)d_in[2];
    const float* x_follower = (const float*)d_in[3];
    const float* Wi1[4] = {(const float*)d_in[4], (const float*)d_in[6],
                           (const float*)d_in[8], (const float*)d_in[10]};
    const float* bi1[4] = {(const float*)d_in[5], (const float*)d_in[7],
                           (const float*)d_in[9], (const float*)d_in[11]};
    const float* Wi2 = (const float*)d_in[12];
    const float* bi2 = (const float*)d_in[13];
    const float* c1W = (const float*)d_in[14];
    const float* c1b = (const float*)d_in[15];
    const float* c2W = (const float*)d_in[16];
    const float* c2b = (const float*)d_in[17];
    const float* Wl[4] = {(const float*)d_in[18], (const float*)d_in[20],
                          (const float*)d_in[22], (const float*)d_in[24]};
    const float* bl[4] = {(const float*)d_in[19], (const float*)d_in[21],
                          (const float*)d_in[23], (const float*)d_in[25]};

    float* out = (float*)d_out;

    float *h, *h2, *agg, *rs;
    cudaGetSymbolAddress((void**)&h,   g_h);
    cudaGetSymbolAddress((void**)&h2,  g_h2);
    cudaGetSymbolAddress((void**)&agg, g_agg);
    cudaGetSymbolAddress((void**)&rs,  g_rs);

    static const int typeOff[4] = {OFF_U, OFF_N, OFF_S, OFF_F};
    static const int typeN[4]   = {NU, NN, NS, NF};
    static const int logOff[4]  = {LOG_U, LOG_N, LOG_S, LOG_F};

    // degrees -> rsqrt(max(deg,1))
    fill0_k<<<512, 256>>>((float4*)rs, RS_TOT / 4);
    count_k<<<(E_POSTS + 255) / 256, 256>>>((const int*)d_in[26], rs + RS_PU,  E_POSTS);
    count_k<<<(E_POSTS + 255) / 256, 256>>>((const int*)d_in[27], rs + RS_PN,  E_POSTS);
    count_k<<<(E_PUB   + 255) / 256, 256>>>((const int*)d_in[28], rs + RS_PS,  E_PUB);
    count_k<<<(E_PUB   + 255) / 256, 256>>>((const int*)d_in[29], rs + RS_PBN, E_PUB);
    count_k<<<(E_FOL   + 255) / 256, 256>>>((const int*)d_in[30], rs + RS_FF,  E_FOL);
    count_k<<<(E_FOL   + 255) / 256, 256>>>((const int*)d_in[31], rs + RS_FU,  E_FOL);
    rsqrt_k<<<(RS_TOT + 255) / 256, 256>>>(rs, RS_TOT);

    // input layer 1 (all on HMMA path; news has K=300 with zero-padded chunks)
    launch_hgemm(x_user,     NU, 128, nullptr, Wi1[0], bi1[0], h + (size_t)OFF_U * 128, 0, 1.0f, 1);
    launch_hgemm(x_news,     NN, 300, nullptr, Wi1[1], bi1[1], h + (size_t)OFF_N * 128, 0, 1.0f, 1);
    launch_hgemm(x_source,   NS, 128, nullptr, Wi1[2], bi1[2], h + (size_t)OFF_S * 128, 0, 1.0f, 1);
    launch_hgemm(x_follower, NF, 128, nullptr, Wi1[3], bi1[3], h + (size_t)OFF_F * 128, 0, 1.0f, 1);

    // input layer 2
    for (int t = 0; t < 4; t++) {
        launch_hgemm(h + (size_t)typeOff[t] * 128, typeN[t], 128, nullptr,
                     Wi2 + (size_t)t * 16384, bi2 + (size_t)t * 128,
                     h2 + (size_t)typeOff[t] * 128, 0, 1.0f, 1);
    }

    // conv1: h2 -> h
    conv_layer(h2, h, c1W, c1b, d_in, agg, rs);

    // conv2: h -> h1 (into d_out)
    float* h1 = out + H1_BASE;
    conv_layer(h, h1, c2W, c2b, d_in, agg, rs);

    // logits
    for (int t = 0; t < 4; t++) {
        logits_k<<<(typeN[t] + 7) / 8, 256>>>(
            h1 + (size_t)typeOff[t] * 128, Wl[t], bl[t],
            out + logOff[t], typeN[t]);
    }
}